// round 13
// baseline (speedup 1.0000x reference)
#include <cuda_runtime.h>
#include <cuda_fp16.h>
#include <math.h>
#include <stdint.h>

#define B_ 4
#define N_ 2048
#define F_ 1024
#define H_ 16
#define D_ 64
#define M_ (B_*N_)   // 8192 rows

// fp16 scratch. g_qh/g_kh: [b,h,n,d]; g_vh: TRANSPOSED [b,h,d,n].
// g_xh: fp16 X [m][k]; g_wh: fp16 W^T per proj [n][k].
__device__ __half g_qh[(size_t)B_*H_*N_*D_];
__device__ __half g_kh[(size_t)B_*H_*N_*D_];
__device__ __half g_vh[(size_t)B_*H_*N_*D_];
__device__ __half g_xh[(size_t)M_*F_];
__device__ __half g_wh[(size_t)3*F_*F_];

__device__ __forceinline__ float ex2f(float x) {
    float y;
    asm("ex2.approx.ftz.f32 %0, %1;" : "=f"(y) : "f"(x));
    return y;
}
__device__ __forceinline__ uint32_t smem_u32(const void* p) {
    uint32_t a;
    asm("{ .reg .u64 t; cvta.to.shared.u64 t, %1; cvt.u32.u64 %0, t; }" : "=r"(a) : "l"(p));
    return a;
}
// pack two fp32 -> fp16x2 (lo = first k element)
__device__ __forceinline__ uint32_t f2h2(float lo, float hi) {
    uint32_t r;
    asm("cvt.rn.f16x2.f32 %0, %1, %2;" : "=r"(r) : "f"(hi), "f"(lo));
    return r;
}
__device__ __forceinline__ void mma16(float& d0, float& d1, float& d2, float& d3,
                                      uint32_t a0, uint32_t a1, uint32_t a2, uint32_t a3,
                                      uint32_t b0, uint32_t b1)
{
    asm volatile("mma.sync.aligned.m16n8k16.row.col.f32.f16.f16.f32 "
                 "{%0,%1,%2,%3}, {%4,%5,%6,%7}, {%8,%9}, {%0,%1,%2,%3};"
                 : "+f"(d0), "+f"(d1), "+f"(d2), "+f"(d3)
                 : "r"(a0), "r"(a1), "r"(a2), "r"(a3), "r"(b0), "r"(b1));
}
__device__ __forceinline__ void ldsm_x4(uint32_t& r0, uint32_t& r1, uint32_t& r2, uint32_t& r3,
                                        uint32_t addr)
{
    asm volatile("ldmatrix.sync.aligned.m8n8.x4.shared.b16 {%0,%1,%2,%3}, [%4];"
                 : "=r"(r0), "=r"(r1), "=r"(r2), "=r"(r3) : "r"(addr));
}
#define CP_ASYNC16(dst, src) \
    asm volatile("cp.async.cg.shared.global [%0], [%1], 16;" :: "r"(dst), "l"(src) : "memory")
#define CP_COMMIT() asm volatile("cp.async.commit_group;" ::: "memory")
#define CP_WAIT0()  asm volatile("cp.async.wait_group 0;" ::: "memory")

#define QSC_ 0.18033688011112042f   // 0.125 * log2(e)

// ---------------------------------------------------------------------------
// Pre-pass: X -> fp16 (8 elems/thread); W -> fp16 W^T.
// ---------------------------------------------------------------------------
__global__ __launch_bounds__(256)
void prep_x(const float* __restrict__ X, __half* __restrict__ Xh)
{
    const size_t i = ((size_t)blockIdx.x * 256 + threadIdx.x) * 8;
    float4 v0 = *(const float4*)(X + i);
    float4 v1 = *(const float4*)(X + i + 4);
    uint4 r;
    r.x = f2h2(v0.x, v0.y);
    r.y = f2h2(v0.z, v0.w);
    r.z = f2h2(v1.x, v1.y);
    r.w = f2h2(v1.z, v1.w);
    *(uint4*)(Xh + i) = r;
}

__global__ __launch_bounds__(256)
void prep_w(const float* __restrict__ Wq, const float* __restrict__ Wk,
            const float* __restrict__ Wv, __half* __restrict__ Wh)
{
    __shared__ float t[32][33];
    const int z = blockIdx.z;
    const float* W = (z == 0) ? Wq : (z == 1) ? Wk : Wv;
    __half* o = Wh + (size_t)z * F_ * F_;
    const int x0 = blockIdx.x * 32, y0 = blockIdx.y * 32;   // x:n, y:k
    const int tx = threadIdx.x, ty = threadIdx.y;
#pragma unroll
    for (int i = 0; i < 32; i += 8)
        t[ty + i][tx] = W[(size_t)(y0 + ty + i) * F_ + x0 + tx];
    __syncthreads();
#pragma unroll
    for (int i = 0; i < 32; i += 8)
        o[(size_t)(x0 + ty + i) * F_ + y0 + tx] = __float2half_rn(t[tx][ty + i]);
}

// ---------------------------------------------------------------------------
// fp16 GEMM: 128x128 tile, BK=64 (4 k16-steps, halves sync count vs BK=32),
// 256 thr (8 warps 2m x 4n), 2-stage cp.async, LDSM fragments, fp32 accum.
// Epilogue: +bias, Q prescale, fp16 out; V written transposed [bh][d][n].
// ---------------------------------------------------------------------------
#define GSTR 72                                   // fp16 units per row (144B)
#define GSTG (128 * GSTR)                         // per operand per stage (u16)
#define GEMM_SMEM (2 * 2 * GSTG * 2)              // 73728 B

__global__ __launch_bounds__(256, 2)
void qkv_gemm_h(const __half* __restrict__ Xh, const __half* __restrict__ Wh,
                const float* __restrict__ bi0, const float* __restrict__ bi1,
                const float* __restrict__ bi2,
                __half* __restrict__ o0, __half* __restrict__ o1,
                __half* __restrict__ o2)
{
    extern __shared__ __align__(16) __half gsm[];
    // layout: [stage][A 128x72 | B 128x72]
    const int z = blockIdx.z;
    const __half* Wz  = Wh + (size_t)z * F_ * F_;
    const float* bias = (z == 0) ? bi0 : (z == 1) ? bi1 : bi2;
    __half* outp      = (z == 0) ? o0 : (z == 1) ? o1 : o2;
    const float sc    = (z == 0) ? QSC_ : 1.0f;

    const int tid  = threadIdx.x;
    const int lane = tid & 31;
    const int wid  = tid >> 5;
    const int wr   = wid & 1;
    const int wc   = wid >> 1;
    const int m0   = blockIdx.y * 128;
    const int n0   = blockIdx.x * 128;
    const int tg   = lane & 3;
    const int gp   = lane >> 2;

    const uint32_t sb = smem_u32(gsm);
    const uint32_t aoff[2] = {0, 2u * GSTG * 2};          // stage byte offsets
    const uint32_t boff = GSTG * 2;                        // B after A in stage

    // loader: 2 thr/row, 64B each (32 fp16)
    const int lr = tid >> 1, lc = (tid & 1) * 32;

    const __half* srcA = Xh + (size_t)(m0 + lr) * F_ + lc;
    const __half* srcB = Wz + (size_t)(n0 + lr) * F_ + lc;

    {   // stage 0
        uint32_t da = sb + (lr * GSTR + lc) * 2;
        uint32_t db = sb + boff + (lr * GSTR + lc) * 2;
#pragma unroll
        for (int i = 0; i < 4; i++) {
            CP_ASYNC16(da + 16 * i, srcA + 8 * i);
            CP_ASYNC16(db + 16 * i, srcB + 8 * i);
        }
    }
    CP_COMMIT();
    CP_WAIT0();
    __syncthreads();

    float c[4][4][4];
#pragma unroll
    for (int i = 0; i < 4; i++)
#pragma unroll
        for (int j = 0; j < 4; j++)
#pragma unroll
            for (int r = 0; r < 4; r++) c[i][j][r] = 0.f;

    // A (Q-style) / B (K-style) LDSM lane maps; col unit = 8 fp16 = 16B
    const int arow8 = ((lane >> 3) & 1) * 8 + (lane & 7);
    const int acol8 = ((lane >> 4) & 1) * 8;
    const int brow8 = ((lane >> 4) & 1) * 8 + (lane & 7);
    const int bcol8 = ((lane >> 3) & 1) * 8;

    int buf = 0;
    const int NT = F_ / 64;   // 16
    for (int kt = 0; kt < NT; kt++) {
        if (kt + 1 < NT) {
            const int kb = (kt + 1) * 64;
            uint32_t da = sb + aoff[buf ^ 1] + (lr * GSTR + lc) * 2;
            uint32_t db = sb + aoff[buf ^ 1] + boff + (lr * GSTR + lc) * 2;
#pragma unroll
            for (int i = 0; i < 4; i++) {
                CP_ASYNC16(da + 16 * i, srcA + kb + 8 * i);
                CP_ASYNC16(db + 16 * i, srcB + kb + 8 * i);
            }
            CP_COMMIT();
        }

        const uint32_t abase = sb + aoff[buf] +
            ((wr * 64 + arow8) * GSTR + acol8) * 2;
        const uint32_t bbase = sb + aoff[buf] + boff +
            ((wc * 32 + brow8) * GSTR + bcol8) * 2;

#pragma unroll
        for (int kk = 0; kk < 64; kk += 16) {
            uint32_t af[4][4], bf[2][4];
#pragma unroll
            for (int mt = 0; mt < 4; mt++)
                ldsm_x4(af[mt][0], af[mt][1], af[mt][2], af[mt][3],
                        abase + (mt * 16 * GSTR + kk) * 2);
#pragma unroll
            for (int h = 0; h < 2; h++)
                ldsm_x4(bf[h][0], bf[h][1], bf[h][2], bf[h][3],
                        bbase + (h * 16 * GSTR + kk) * 2);
#pragma unroll
            for (int mt = 0; mt < 4; mt++)
#pragma unroll
                for (int h = 0; h < 2; h++) {
                    mma16(c[mt][2*h][0], c[mt][2*h][1], c[mt][2*h][2], c[mt][2*h][3],
                          af[mt][0], af[mt][1], af[mt][2], af[mt][3],
                          bf[h][0], bf[h][1]);
                    mma16(c[mt][2*h+1][0], c[mt][2*h+1][1], c[mt][2*h+1][2], c[mt][2*h+1][3],
                          af[mt][0], af[mt][1], af[mt][2], af[mt][3],
                          bf[h][2], bf[h][3]);
                }
        }

        if (kt + 1 < NT) {
            CP_WAIT0();
            __syncthreads();
            buf ^= 1;
        }
    }

    // epilogue
#pragma unroll
    for (int mt = 0; mt < 4; mt++) {
#pragma unroll
        for (int nt = 0; nt < 4; nt++) {
            const int j  = n0 + wc * 32 + nt * 8 + tg * 2;
            const int h  = j >> 6, dd = j & 63;
            const float bj0 = bias[j], bj1 = bias[j + 1];
            const int m  = m0 + wr * 64 + mt * 16 + gp;
            const int bb = m >> 11, nn = m & 2047;
            const float r00 = (c[mt][nt][0] + bj0) * sc;
            const float r01 = (c[mt][nt][1] + bj1) * sc;
            const float r10 = (c[mt][nt][2] + bj0) * sc;
            const float r11 = (c[mt][nt][3] + bj1) * sc;
            if (z == 2) {
                __half* bp = outp + (((size_t)(bb * H_ + h)) * D_ + dd) * N_ + nn;
                bp[0]      = __float2half_rn(r00);   // (dd,   nn)
                bp[N_]     = __float2half_rn(r01);   // (dd+1, nn)
                bp[8]      = __float2half_rn(r10);   // (dd,   nn+8)
                bp[N_ + 8] = __float2half_rn(r11);
            } else {
                __half* bp = outp + (((size_t)(bb * H_ + h)) * N_ + nn) * D_ + dd;
                *(uint32_t*)bp = f2h2(r00, r01);
                *(uint32_t*)(bp + 8 * (size_t)D_) = f2h2(r10, r11);
            }
        }
    }
}

// ---------------------------------------------------------------------------
// fp16 flash attention (unchanged from round 12, passing, 144.9us).
// ---------------------------------------------------------------------------
#define FSTR 72                                  // fp16 units per row (144B)
#define FLASH_SMEM ((128*FSTR + 2*64*FSTR + 2*64*FSTR) * 2)   // 36864 B

__global__ __launch_bounds__(256, 2)
void flash_h(const __half* __restrict__ gq, const __half* __restrict__ gk,
             const __half* __restrict__ gvt, float* __restrict__ out)
{
    extern __shared__ __align__(16) __half fsm[];
    const uint32_t qs_base = smem_u32(fsm);
    const uint32_t ks_base = qs_base + 128 * FSTR * 2;
    const uint32_t vt_base = ks_base + 2 * 64 * FSTR * 2;

    const int tid = threadIdx.x, lane = tid & 31, wid = tid >> 5;
    const int gp = lane >> 2, tg = lane & 3;
    const int qt = (int)gridDim.x - 1 - (int)blockIdx.x;  // heavy tiles first
    const int bh = blockIdx.y;
    const int n0 = qt * 128;
    const int nkt = 2 * qt + 2;

    const __half* qb  = gq  + (size_t)bh * (N_ * D_);
    const __half* kb  = gk  + (size_t)bh * (N_ * D_);
    const __half* vtb = gvt + (size_t)bh * (D_ * N_);

    const int kr = tid >> 2, kc = (tid & 3) * 16;   // K/Vt: 4 thr/row, 16 fp16
    const int qr = tid >> 1, qc = (tid & 1) * 32;   // Q: 2 thr/row, 32 fp16

    {
        const __half* src = qb + (size_t)(n0 + qr) * D_ + qc;
        uint32_t dst = qs_base + (qr * FSTR + qc) * 2;
#pragma unroll
        for (int i = 0; i < 4; i++) CP_ASYNC16(dst + 16 * i, src + 8 * i);
    }
    {
        const __half* src = kb + (size_t)kr * D_ + kc;
        uint32_t dst = ks_base + (kr * FSTR + kc) * 2;
        CP_ASYNC16(dst, src); CP_ASYNC16(dst + 16, src + 8);
    }
    {
        const __half* src = vtb + (size_t)kr * N_ + kc;
        uint32_t dst = vt_base + (kr * FSTR + kc) * 2;
        CP_ASYNC16(dst, src); CP_ASYNC16(dst + 16, src + 8);
    }
    CP_COMMIT();
    CP_WAIT0();
    __syncthreads();

    uint32_t qf[4][4];
    {
        const int qrow = wid * 16 + ((lane >> 3) & 1) * 8 + (lane & 7);
        const int qcol = ((lane >> 4) & 1) * 8;
        const uint32_t qaddr = qs_base + (qrow * FSTR + qcol) * 2;
#pragma unroll
        for (int ks = 0; ks < 4; ks++)
            ldsm_x4(qf[ks][0], qf[ks][1], qf[ks][2], qf[ks][3],
                    qaddr + (ks * 16) * 2);
    }

    const int brow8 = ((lane >> 4) & 1) * 8 + (lane & 7);
    const int bcol8 = ((lane >> 3) & 1) * 8;

    float m0r = -1e30f, m1r = -1e30f, l0 = 0.f, l1 = 0.f;
    float o[8][4];
#pragma unroll
    for (int nt = 0; nt < 8; nt++)
#pragma unroll
        for (int e = 0; e < 4; e++) o[nt][e] = 0.f;

    int buf = 0;
    for (int kt = 0; kt < nkt; kt++) {
        const int c0 = kt * 64;
        const int more = (kt + 1 < nkt);

        if (more) {
            {
                const __half* src = kb + (size_t)(c0 + 64 + kr) * D_ + kc;
                uint32_t dst = ks_base + ((buf ^ 1) * 64 * FSTR + kr * FSTR + kc) * 2;
                CP_ASYNC16(dst, src); CP_ASYNC16(dst + 16, src + 8);
            }
            {
                const __half* src = vtb + (size_t)kr * N_ + c0 + 64 + kc;
                uint32_t dst = vt_base + ((buf ^ 1) * 64 * FSTR + kr * FSTR + kc) * 2;
                CP_ASYNC16(dst, src); CP_ASYNC16(dst + 16, src + 8);
            }
            CP_COMMIT();
        }

        float s[8][4];
#pragma unroll
        for (int nt = 0; nt < 8; nt++)
#pragma unroll
            for (int e = 0; e < 4; e++) s[nt][e] = 0.f;

        const uint32_t kaddr = ks_base + (buf * 64 * FSTR + brow8 * FSTR + bcol8) * 2;
#pragma unroll
        for (int n = 0; n < 4; n++) {
            const uint32_t an = kaddr + (n * 16 * FSTR) * 2;
#pragma unroll
            for (int ks = 0; ks < 4; ks++) {
                uint32_t b0a, b1a, b0b, b1b;
                ldsm_x4(b0a, b1a, b0b, b1b, an + (ks * 16) * 2);
                mma16(s[2*n][0], s[2*n][1], s[2*n][2], s[2*n][3],
                      qf[ks][0], qf[ks][1], qf[ks][2], qf[ks][3], b0a, b1a);
                mma16(s[2*n+1][0], s[2*n+1][1], s[2*n+1][2], s[2*n+1][3],
                      qf[ks][0], qf[ks][1], qf[ks][2], qf[ks][3], b0b, b1b);
            }
        }

        const int r0 = wid * 16 + gp;
        if (kt >= 2 * qt) {
            const int i0g = n0 + r0, i1g = i0g + 8;
#pragma unroll
            for (int nt = 0; nt < 8; nt++) {
                const int j0 = c0 + nt * 8 + 2 * tg;
                if (j0     > i0g) s[nt][0] = -1e30f;
                if (j0 + 1 > i0g) s[nt][1] = -1e30f;
                if (j0     > i1g) s[nt][2] = -1e30f;
                if (j0 + 1 > i1g) s[nt][3] = -1e30f;
            }
        }

        float mx0 = -1e30f, mx1 = -1e30f;
#pragma unroll
        for (int nt = 0; nt < 8; nt++) {
            mx0 = fmaxf(mx0, fmaxf(s[nt][0], s[nt][1]));
            mx1 = fmaxf(mx1, fmaxf(s[nt][2], s[nt][3]));
        }
        mx0 = fmaxf(mx0, __shfl_xor_sync(0xffffffffu, mx0, 1));
        mx0 = fmaxf(mx0, __shfl_xor_sync(0xffffffffu, mx0, 2));
        mx1 = fmaxf(mx1, __shfl_xor_sync(0xffffffffu, mx1, 1));
        mx1 = fmaxf(mx1, __shfl_xor_sync(0xffffffffu, mx1, 2));

        const float mn0 = fmaxf(m0r, mx0), mn1 = fmaxf(m1r, mx1);
        const float al0 = ex2f(m0r - mn0), al1 = ex2f(m1r - mn1);
        m0r = mn0; m1r = mn1;

        float ls0 = 0.f, ls1 = 0.f;
#pragma unroll
        for (int nt = 0; nt < 8; nt++) {
            s[nt][0] = ex2f(s[nt][0] - mn0);
            s[nt][1] = ex2f(s[nt][1] - mn0);
            s[nt][2] = ex2f(s[nt][2] - mn1);
            s[nt][3] = ex2f(s[nt][3] - mn1);
            ls0 += s[nt][0] + s[nt][1];
            ls1 += s[nt][2] + s[nt][3];
        }
        ls0 += __shfl_xor_sync(0xffffffffu, ls0, 1);
        ls0 += __shfl_xor_sync(0xffffffffu, ls0, 2);
        ls1 += __shfl_xor_sync(0xffffffffu, ls1, 1);
        ls1 += __shfl_xor_sync(0xffffffffu, ls1, 2);
        l0 = l0 * al0 + ls0;
        l1 = l1 * al1 + ls1;
#pragma unroll
        for (int nt = 0; nt < 8; nt++) {
            o[nt][0] *= al0; o[nt][1] *= al0;
            o[nt][2] *= al1; o[nt][3] *= al1;
        }

        const uint32_t vaddr = vt_base + (buf * 64 * FSTR + brow8 * FSTR + bcol8) * 2;
#pragma unroll
        for (int ks = 0; ks < 4; ks++) {
            const uint32_t a0 = f2h2(s[2*ks][0],   s[2*ks][1]);
            const uint32_t a1 = f2h2(s[2*ks][2],   s[2*ks][3]);
            const uint32_t a2 = f2h2(s[2*ks+1][0], s[2*ks+1][1]);
            const uint32_t a3 = f2h2(s[2*ks+1][2], s[2*ks+1][3]);
#pragma unroll
            for (int n = 0; n < 4; n++) {
                uint32_t b0a, b1a, b0b, b1b;
                ldsm_x4(b0a, b1a, b0b, b1b,
                        vaddr + (n * 16 * FSTR + ks * 16) * 2);
                mma16(o[2*n][0], o[2*n][1], o[2*n][2], o[2*n][3],
                      a0, a1, a2, a3, b0a, b1a);
                mma16(o[2*n+1][0], o[2*n+1][1], o[2*n+1][2], o[2*n+1][3],
                      a0, a1, a2, a3, b0b, b1b);
            }
        }

        if (more) {
            CP_WAIT0();
            __syncthreads();
            buf ^= 1;
        }
    }

    const int r0 = wid * 16 + gp;
    const float inv0 = 1.f / l0, inv1 = 1.f / l1;
    const int bb = bh >> 4, h = bh & 15;
    float* base = out + ((size_t)(bb * N_ + n0 + r0)) * F_ + h * D_;
#pragma unroll
    for (int nt = 0; nt < 8; nt++) {
        const int d = nt * 8 + 2 * tg;
        *(float2*)(base + d) = make_float2(o[nt][0] * inv0, o[nt][1] * inv0);
        *(float2*)(base + 8 * F_ + d) = make_float2(o[nt][2] * inv1, o[nt][3] * inv1);
    }
}

// ---------------------------------------------------------------------------
extern "C" void kernel_launch(void* const* d_in, const int* in_sizes, int n_in,
                              void* d_out, int out_size)
{
    const float* x  = (const float*)d_in[0];
    const float* Wq = (const float*)d_in[1];
    const float* bq = (const float*)d_in[2];
    const float* Wk = (const float*)d_in[3];
    const float* bk = (const float*)d_in[4];
    const float* Wv = (const float*)d_in[5];
    const float* bv = (const float*)d_in[6];
    float* out = (float*)d_out;
    (void)in_sizes; (void)n_in; (void)out_size;

    __half *pq = nullptr, *pk = nullptr, *pv = nullptr, *pxh = nullptr, *pwh = nullptr;
    cudaGetSymbolAddress((void**)&pq, g_qh);
    cudaGetSymbolAddress((void**)&pk, g_kh);
    cudaGetSymbolAddress((void**)&pv, g_vh);
    cudaGetSymbolAddress((void**)&pxh, g_xh);
    cudaGetSymbolAddress((void**)&pwh, g_wh);

    // 1) pre-pass: fp16 conversions
    prep_x<<<(M_ * F_ / 8) / 256, 256>>>(x, pxh);
    prep_w<<<dim3(32, 32, 3), dim3(32, 8)>>>(Wq, Wk, Wv, pwh);

    // 2) fp16 QKV projections (BK=64)
    cudaFuncSetAttribute(qkv_gemm_h,
                         cudaFuncAttributeMaxDynamicSharedMemorySize, GEMM_SMEM);
    qkv_gemm_h<<<dim3(F_ / 128, M_ / 128, 3), 256, GEMM_SMEM>>>(
        pxh, pwh, bq, bk, bv, pq, pk, pv);

    // 3) fp16 causal flash attention
    cudaFuncSetAttribute(flash_h,
                         cudaFuncAttributeMaxDynamicSharedMemorySize, FLASH_SMEM);
    flash_h<<<dim3(N_ / 128, B_ * H_), 256, FLASH_SMEM>>>(pq, pk, pv, out);
}

// round 14
// speedup vs baseline: 1.0562x; 1.0562x over previous
#include <cuda_runtime.h>
#include <cuda_fp16.h>
#include <math.h>
#include <stdint.h>

#define B_ 4
#define N_ 2048
#define F_ 1024
#define H_ 16
#define D_ 64
#define M_ (B_*N_)   // 8192 rows

// fp16 scratch. g_qh/g_kh: [b,h,n,d]; g_vh: TRANSPOSED [b,h,d,n].
// g_xh: fp16 X [m][k]; g_wh: fp16 W^T per proj [n][k].
__device__ __half g_qh[(size_t)B_*H_*N_*D_];
__device__ __half g_kh[(size_t)B_*H_*N_*D_];
__device__ __half g_vh[(size_t)B_*H_*N_*D_];
__device__ __half g_xh[(size_t)M_*F_];
__device__ __half g_wh[(size_t)3*F_*F_];

__device__ __forceinline__ float ex2f(float x) {
    float y;
    asm("ex2.approx.ftz.f32 %0, %1;" : "=f"(y) : "f"(x));
    return y;
}
__device__ __forceinline__ uint32_t smem_u32(const void* p) {
    uint32_t a;
    asm("{ .reg .u64 t; cvta.to.shared.u64 t, %1; cvt.u32.u64 %0, t; }" : "=r"(a) : "l"(p));
    return a;
}
// pack two fp32 -> fp16x2 (lo = first k element)
__device__ __forceinline__ uint32_t f2h2(float lo, float hi) {
    uint32_t r;
    asm("cvt.rn.f16x2.f32 %0, %1, %2;" : "=r"(r) : "f"(hi), "f"(lo));
    return r;
}
__device__ __forceinline__ void mma16(float& d0, float& d1, float& d2, float& d3,
                                      uint32_t a0, uint32_t a1, uint32_t a2, uint32_t a3,
                                      uint32_t b0, uint32_t b1)
{
    asm volatile("mma.sync.aligned.m16n8k16.row.col.f32.f16.f16.f32 "
                 "{%0,%1,%2,%3}, {%4,%5,%6,%7}, {%8,%9}, {%0,%1,%2,%3};"
                 : "+f"(d0), "+f"(d1), "+f"(d2), "+f"(d3)
                 : "r"(a0), "r"(a1), "r"(a2), "r"(a3), "r"(b0), "r"(b1));
}
__device__ __forceinline__ void ldsm_x4(uint32_t& r0, uint32_t& r1, uint32_t& r2, uint32_t& r3,
                                        uint32_t addr)
{
    asm volatile("ldmatrix.sync.aligned.m8n8.x4.shared.b16 {%0,%1,%2,%3}, [%4];"
                 : "=r"(r0), "=r"(r1), "=r"(r2), "=r"(r3) : "r"(addr));
}
#define CP_ASYNC16(dst, src) \
    asm volatile("cp.async.cg.shared.global [%0], [%1], 16;" :: "r"(dst), "l"(src) : "memory")
#define CP_COMMIT() asm volatile("cp.async.commit_group;" ::: "memory")
#define CP_WAIT0()  asm volatile("cp.async.wait_group 0;" ::: "memory")
#define CP_WAIT1()  asm volatile("cp.async.wait_group 1;" ::: "memory")

#define QSC_ 0.18033688011112042f   // 0.125 * log2(e)

// ---------------------------------------------------------------------------
// Pre-pass: X -> fp16 (8 elems/thread); W -> fp16 W^T.
// ---------------------------------------------------------------------------
__global__ __launch_bounds__(256)
void prep_x(const float* __restrict__ X, __half* __restrict__ Xh)
{
    const size_t i = ((size_t)blockIdx.x * 256 + threadIdx.x) * 8;
    float4 v0 = *(const float4*)(X + i);
    float4 v1 = *(const float4*)(X + i + 4);
    uint4 r;
    r.x = f2h2(v0.x, v0.y);
    r.y = f2h2(v0.z, v0.w);
    r.z = f2h2(v1.x, v1.y);
    r.w = f2h2(v1.z, v1.w);
    *(uint4*)(Xh + i) = r;
}

__global__ __launch_bounds__(256)
void prep_w(const float* __restrict__ Wq, const float* __restrict__ Wk,
            const float* __restrict__ Wv, __half* __restrict__ Wh)
{
    __shared__ float t[32][33];
    const int z = blockIdx.z;
    const float* W = (z == 0) ? Wq : (z == 1) ? Wk : Wv;
    __half* o = Wh + (size_t)z * F_ * F_;
    const int x0 = blockIdx.x * 32, y0 = blockIdx.y * 32;   // x:n, y:k
    const int tx = threadIdx.x, ty = threadIdx.y;
#pragma unroll
    for (int i = 0; i < 32; i += 8)
        t[ty + i][tx] = W[(size_t)(y0 + ty + i) * F_ + x0 + tx];
    __syncthreads();
#pragma unroll
    for (int i = 0; i < 32; i += 8)
        o[(size_t)(x0 + ty + i) * F_ + y0 + tx] = __float2half_rn(t[tx][ty + i]);
}

// ---------------------------------------------------------------------------
// fp16 GEMM: 128x128 tile, BK=32 (round-12 config), 256 thr (8 warps 2m x 4n),
// THREE-stage cp.async pipeline with wait_group 1 (one copy always in flight),
// LDSM fragments, fp32 accum. Epilogue: +bias, Q prescale, fp16 out;
// V written transposed [bh][d][n].
// ---------------------------------------------------------------------------
#define GSTR 40                                   // fp16 units per row (80B)
#define GSTG (128 * GSTR)                         // per operand per stage (u16)
#define GSTAGE_B (2 * GSTG * 2)                   // stage bytes (A+B) = 20480
#define GEMM_SMEM (3 * GSTAGE_B)                  // 61440 B

__global__ __launch_bounds__(256, 2)
void qkv_gemm_h(const __half* __restrict__ Xh, const __half* __restrict__ Wh,
                const float* __restrict__ bi0, const float* __restrict__ bi1,
                const float* __restrict__ bi2,
                __half* __restrict__ o0, __half* __restrict__ o1,
                __half* __restrict__ o2)
{
    extern __shared__ __align__(16) __half gsm[];
    // layout: [stage][A 128x40 | B 128x40] x 3
    const int z = blockIdx.z;
    const __half* Wz  = Wh + (size_t)z * F_ * F_;
    const float* bias = (z == 0) ? bi0 : (z == 1) ? bi1 : bi2;
    __half* outp      = (z == 0) ? o0 : (z == 1) ? o1 : o2;
    const float sc    = (z == 0) ? QSC_ : 1.0f;

    const int tid  = threadIdx.x;
    const int lane = tid & 31;
    const int wid  = tid >> 5;
    const int wr   = wid & 1;
    const int wc   = wid >> 1;
    const int m0   = blockIdx.y * 128;
    const int n0   = blockIdx.x * 128;
    const int tg   = lane & 3;
    const int gp   = lane >> 2;

    const uint32_t sb = smem_u32(gsm);
    const uint32_t boff = GSTG * 2;                // B after A within a stage

    // loader: 2 thr/row, 32B each (16 fp16)
    const int lr = tid >> 1, lc = (tid & 1) * 16;

    const __half* srcA = Xh + (size_t)(m0 + lr) * F_ + lc;
    const __half* srcB = Wz + (size_t)(n0 + lr) * F_ + lc;

    // prologue: stages 0, 1
#pragma unroll
    for (int s = 0; s < 2; s++) {
        const int kb = s * 32;
        uint32_t da = sb + s * GSTAGE_B + (lr * GSTR + lc) * 2;
        CP_ASYNC16(da, srcA + kb); CP_ASYNC16(da + 16, srcA + kb + 8);
        uint32_t db = sb + s * GSTAGE_B + boff + (lr * GSTR + lc) * 2;
        CP_ASYNC16(db, srcB + kb); CP_ASYNC16(db + 16, srcB + kb + 8);
        CP_COMMIT();
    }

    float c[4][4][4];
#pragma unroll
    for (int i = 0; i < 4; i++)
#pragma unroll
        for (int j = 0; j < 4; j++)
#pragma unroll
            for (int r = 0; r < 4; r++) c[i][j][r] = 0.f;

    // A (Q-style) / B (K-style) LDSM lane maps; col unit = 8 fp16 = 16B
    const int arow8 = ((lane >> 3) & 1) * 8 + (lane & 7);
    const int acol8 = ((lane >> 4) & 1) * 8;
    const int brow8 = ((lane >> 4) & 1) * 8 + (lane & 7);
    const int bcol8 = ((lane >> 3) & 1) * 8;

    const int NT = F_ / 32;   // 32
    for (int kt = 0; kt < NT; kt++) {
        if (kt + 1 < NT) CP_WAIT1(); else CP_WAIT0();   // stage kt resident
        __syncthreads();                                 // prev compute done

        if (kt + 2 < NT) {   // issue stage kt+2 into buffer (kt+2)%3
            const int s = (kt + 2) % 3;
            const int kb = (kt + 2) * 32;
            uint32_t da = sb + s * GSTAGE_B + (lr * GSTR + lc) * 2;
            CP_ASYNC16(da, srcA + kb); CP_ASYNC16(da + 16, srcA + kb + 8);
            uint32_t db = sb + s * GSTAGE_B + boff + (lr * GSTR + lc) * 2;
            CP_ASYNC16(db, srcB + kb); CP_ASYNC16(db + 16, srcB + kb + 8);
            CP_COMMIT();
        }

        const int s = kt % 3;
        const uint32_t abase = sb + s * GSTAGE_B +
            ((wr * 64 + arow8) * GSTR + acol8) * 2;
        const uint32_t bbase = sb + s * GSTAGE_B + boff +
            ((wc * 32 + brow8) * GSTR + bcol8) * 2;

#pragma unroll
        for (int kk = 0; kk < 32; kk += 16) {
            uint32_t af[4][4], bf[2][4];
#pragma unroll
            for (int mt = 0; mt < 4; mt++)
                ldsm_x4(af[mt][0], af[mt][1], af[mt][2], af[mt][3],
                        abase + (mt * 16 * GSTR + kk) * 2);
#pragma unroll
            for (int h = 0; h < 2; h++)
                ldsm_x4(bf[h][0], bf[h][1], bf[h][2], bf[h][3],
                        bbase + (h * 16 * GSTR + kk) * 2);
#pragma unroll
            for (int mt = 0; mt < 4; mt++)
#pragma unroll
                for (int h = 0; h < 2; h++) {
                    mma16(c[mt][2*h][0], c[mt][2*h][1], c[mt][2*h][2], c[mt][2*h][3],
                          af[mt][0], af[mt][1], af[mt][2], af[mt][3],
                          bf[h][0], bf[h][1]);
                    mma16(c[mt][2*h+1][0], c[mt][2*h+1][1], c[mt][2*h+1][2], c[mt][2*h+1][3],
                          af[mt][0], af[mt][1], af[mt][2], af[mt][3],
                          bf[h][2], bf[h][3]);
                }
        }
    }

    // epilogue
#pragma unroll
    for (int mt = 0; mt < 4; mt++) {
#pragma unroll
        for (int nt = 0; nt < 4; nt++) {
            const int j  = n0 + wc * 32 + nt * 8 + tg * 2;
            const int h  = j >> 6, dd = j & 63;
            const float bj0 = bias[j], bj1 = bias[j + 1];
            const int m  = m0 + wr * 64 + mt * 16 + gp;
            const int bb = m >> 11, nn = m & 2047;
            const float r00 = (c[mt][nt][0] + bj0) * sc;
            const float r01 = (c[mt][nt][1] + bj1) * sc;
            const float r10 = (c[mt][nt][2] + bj0) * sc;
            const float r11 = (c[mt][nt][3] + bj1) * sc;
            if (z == 2) {
                __half* bp = outp + (((size_t)(bb * H_ + h)) * D_ + dd) * N_ + nn;
                bp[0]      = __float2half_rn(r00);   // (dd,   nn)
                bp[N_]     = __float2half_rn(r01);   // (dd+1, nn)
                bp[8]      = __float2half_rn(r10);   // (dd,   nn+8)
                bp[N_ + 8] = __float2half_rn(r11);
            } else {
                __half* bp = outp + (((size_t)(bb * H_ + h)) * N_ + nn) * D_ + dd;
                *(uint32_t*)bp = f2h2(r00, r01);
                *(uint32_t*)(bp + 8 * (size_t)D_) = f2h2(r10, r11);
            }
        }
    }
}

// ---------------------------------------------------------------------------
// fp16 flash attention (unchanged from round 12, passing, 144.9us).
// ---------------------------------------------------------------------------
#define FSTR 72                                  // fp16 units per row (144B)
#define FLASH_SMEM ((128*FSTR + 2*64*FSTR + 2*64*FSTR) * 2)   // 36864 B

__global__ __launch_bounds__(256, 2)
void flash_h(const __half* __restrict__ gq, const __half* __restrict__ gk,
             const __half* __restrict__ gvt, float* __restrict__ out)
{
    extern __shared__ __align__(16) __half fsm[];
    const uint32_t qs_base = smem_u32(fsm);
    const uint32_t ks_base = qs_base + 128 * FSTR * 2;
    const uint32_t vt_base = ks_base + 2 * 64 * FSTR * 2;

    const int tid = threadIdx.x, lane = tid & 31, wid = tid >> 5;
    const int gp = lane >> 2, tg = lane & 3;
    const int qt = (int)gridDim.x - 1 - (int)blockIdx.x;  // heavy tiles first
    const int bh = blockIdx.y;
    const int n0 = qt * 128;
    const int nkt = 2 * qt + 2;

    const __half* qb  = gq  + (size_t)bh * (N_ * D_);
    const __half* kb  = gk  + (size_t)bh * (N_ * D_);
    const __half* vtb = gvt + (size_t)bh * (D_ * N_);

    const int kr = tid >> 2, kc = (tid & 3) * 16;   // K/Vt: 4 thr/row, 16 fp16
    const int qr = tid >> 1, qc = (tid & 1) * 32;   // Q: 2 thr/row, 32 fp16

    {
        const __half* src = qb + (size_t)(n0 + qr) * D_ + qc;
        uint32_t dst = qs_base + (qr * FSTR + qc) * 2;
#pragma unroll
        for (int i = 0; i < 4; i++) CP_ASYNC16(dst + 16 * i, src + 8 * i);
    }
    {
        const __half* src = kb + (size_t)kr * D_ + kc;
        uint32_t dst = ks_base + (kr * FSTR + kc) * 2;
        CP_ASYNC16(dst, src); CP_ASYNC16(dst + 16, src + 8);
    }
    {
        const __half* src = vtb + (size_t)kr * N_ + kc;
        uint32_t dst = vt_base + (kr * FSTR + kc) * 2;
        CP_ASYNC16(dst, src); CP_ASYNC16(dst + 16, src + 8);
    }
    CP_COMMIT();
    CP_WAIT0();
    __syncthreads();

    uint32_t qf[4][4];
    {
        const int qrow = wid * 16 + ((lane >> 3) & 1) * 8 + (lane & 7);
        const int qcol = ((lane >> 4) & 1) * 8;
        const uint32_t qaddr = qs_base + (qrow * FSTR + qcol) * 2;
#pragma unroll
        for (int ks = 0; ks < 4; ks++)
            ldsm_x4(qf[ks][0], qf[ks][1], qf[ks][2], qf[ks][3],
                    qaddr + (ks * 16) * 2);
    }

    const int brow8 = ((lane >> 4) & 1) * 8 + (lane & 7);
    const int bcol8 = ((lane >> 3) & 1) * 8;

    float m0r = -1e30f, m1r = -1e30f, l0 = 0.f, l1 = 0.f;
    float o[8][4];
#pragma unroll
    for (int nt = 0; nt < 8; nt++)
#pragma unroll
        for (int e = 0; e < 4; e++) o[nt][e] = 0.f;

    int buf = 0;
    for (int kt = 0; kt < nkt; kt++) {
        const int c0 = kt * 64;
        const int more = (kt + 1 < nkt);

        if (more) {
            {
                const __half* src = kb + (size_t)(c0 + 64 + kr) * D_ + kc;
                uint32_t dst = ks_base + ((buf ^ 1) * 64 * FSTR + kr * FSTR + kc) * 2;
                CP_ASYNC16(dst, src); CP_ASYNC16(dst + 16, src + 8);
            }
            {
                const __half* src = vtb + (size_t)kr * N_ + c0 + 64 + kc;
                uint32_t dst = vt_base + ((buf ^ 1) * 64 * FSTR + kr * FSTR + kc) * 2;
                CP_ASYNC16(dst, src); CP_ASYNC16(dst + 16, src + 8);
            }
            CP_COMMIT();
        }

        float s[8][4];
#pragma unroll
        for (int nt = 0; nt < 8; nt++)
#pragma unroll
            for (int e = 0; e < 4; e++) s[nt][e] = 0.f;

        const uint32_t kaddr = ks_base + (buf * 64 * FSTR + brow8 * FSTR + bcol8) * 2;
#pragma unroll
        for (int n = 0; n < 4; n++) {
            const uint32_t an = kaddr + (n * 16 * FSTR) * 2;
#pragma unroll
            for (int ks = 0; ks < 4; ks++) {
                uint32_t b0a, b1a, b0b, b1b;
                ldsm_x4(b0a, b1a, b0b, b1b, an + (ks * 16) * 2);
                mma16(s[2*n][0], s[2*n][1], s[2*n][2], s[2*n][3],
                      qf[ks][0], qf[ks][1], qf[ks][2], qf[ks][3], b0a, b1a);
                mma16(s[2*n+1][0], s[2*n+1][1], s[2*n+1][2], s[2*n+1][3],
                      qf[ks][0], qf[ks][1], qf[ks][2], qf[ks][3], b0b, b1b);
            }
        }

        const int r0 = wid * 16 + gp;
        if (kt >= 2 * qt) {
            const int i0g = n0 + r0, i1g = i0g + 8;
#pragma unroll
            for (int nt = 0; nt < 8; nt++) {
                const int j0 = c0 + nt * 8 + 2 * tg;
                if (j0     > i0g) s[nt][0] = -1e30f;
                if (j0 + 1 > i0g) s[nt][1] = -1e30f;
                if (j0     > i1g) s[nt][2] = -1e30f;
                if (j0 + 1 > i1g) s[nt][3] = -1e30f;
            }
        }

        float mx0 = -1e30f, mx1 = -1e30f;
#pragma unroll
        for (int nt = 0; nt < 8; nt++) {
            mx0 = fmaxf(mx0, fmaxf(s[nt][0], s[nt][1]));
            mx1 = fmaxf(mx1, fmaxf(s[nt][2], s[nt][3]));
        }
        mx0 = fmaxf(mx0, __shfl_xor_sync(0xffffffffu, mx0, 1));
        mx0 = fmaxf(mx0, __shfl_xor_sync(0xffffffffu, mx0, 2));
        mx1 = fmaxf(mx1, __shfl_xor_sync(0xffffffffu, mx1, 1));
        mx1 = fmaxf(mx1, __shfl_xor_sync(0xffffffffu, mx1, 2));

        const float mn0 = fmaxf(m0r, mx0), mn1 = fmaxf(m1r, mx1);
        const float al0 = ex2f(m0r - mn0), al1 = ex2f(m1r - mn1);
        m0r = mn0; m1r = mn1;

        float ls0 = 0.f, ls1 = 0.f;
#pragma unroll
        for (int nt = 0; nt < 8; nt++) {
            s[nt][0] = ex2f(s[nt][0] - mn0);
            s[nt][1] = ex2f(s[nt][1] - mn0);
            s[nt][2] = ex2f(s[nt][2] - mn1);
            s[nt][3] = ex2f(s[nt][3] - mn1);
            ls0 += s[nt][0] + s[nt][1];
            ls1 += s[nt][2] + s[nt][3];
        }
        ls0 += __shfl_xor_sync(0xffffffffu, ls0, 1);
        ls0 += __shfl_xor_sync(0xffffffffu, ls0, 2);
        ls1 += __shfl_xor_sync(0xffffffffu, ls1, 1);
        ls1 += __shfl_xor_sync(0xffffffffu, ls1, 2);
        l0 = l0 * al0 + ls0;
        l1 = l1 * al1 + ls1;
#pragma unroll
        for (int nt = 0; nt < 8; nt++) {
            o[nt][0] *= al0; o[nt][1] *= al0;
            o[nt][2] *= al1; o[nt][3] *= al1;
        }

        const uint32_t vaddr = vt_base + (buf * 64 * FSTR + brow8 * FSTR + bcol8) * 2;
#pragma unroll
        for (int ks = 0; ks < 4; ks++) {
            const uint32_t a0 = f2h2(s[2*ks][0],   s[2*ks][1]);
            const uint32_t a1 = f2h2(s[2*ks][2],   s[2*ks][3]);
            const uint32_t a2 = f2h2(s[2*ks+1][0], s[2*ks+1][1]);
            const uint32_t a3 = f2h2(s[2*ks+1][2], s[2*ks+1][3]);
#pragma unroll
            for (int n = 0; n < 4; n++) {
                uint32_t b0a, b1a, b0b, b1b;
                ldsm_x4(b0a, b1a, b0b, b1b,
                        vaddr + (n * 16 * FSTR + ks * 16) * 2);
                mma16(o[2*n][0], o[2*n][1], o[2*n][2], o[2*n][3],
                      a0, a1, a2, a3, b0a, b1a);
                mma16(o[2*n+1][0], o[2*n+1][1], o[2*n+1][2], o[2*n+1][3],
                      a0, a1, a2, a3, b0b, b1b);
            }
        }

        if (more) {
            CP_WAIT0();
            __syncthreads();
            buf ^= 1;
        }
    }

    const int r0 = wid * 16 + gp;
    const float inv0 = 1.f / l0, inv1 = 1.f / l1;
    const int bb = bh >> 4, h = bh & 15;
    float* base = out + ((size_t)(bb * N_ + n0 + r0)) * F_ + h * D_;
#pragma unroll
    for (int nt = 0; nt < 8; nt++) {
        const int d = nt * 8 + 2 * tg;
        *(float2*)(base + d) = make_float2(o[nt][0] * inv0, o[nt][1] * inv0);
        *(float2*)(base + 8 * F_ + d) = make_float2(o[nt][2] * inv1, o[nt][3] * inv1);
    }
}

// ---------------------------------------------------------------------------
extern "C" void kernel_launch(void* const* d_in, const int* in_sizes, int n_in,
                              void* d_out, int out_size)
{
    const float* x  = (const float*)d_in[0];
    const float* Wq = (const float*)d_in[1];
    const float* bq = (const float*)d_in[2];
    const float* Wk = (const float*)d_in[3];
    const float* bk = (const float*)d_in[4];
    const float* Wv = (const float*)d_in[5];
    const float* bv = (const float*)d_in[6];
    float* out = (float*)d_out;
    (void)in_sizes; (void)n_in; (void)out_size;

    __half *pq = nullptr, *pk = nullptr, *pv = nullptr, *pxh = nullptr, *pwh = nullptr;
    cudaGetSymbolAddress((void**)&pq, g_qh);
    cudaGetSymbolAddress((void**)&pk, g_kh);
    cudaGetSymbolAddress((void**)&pv, g_vh);
    cudaGetSymbolAddress((void**)&pxh, g_xh);
    cudaGetSymbolAddress((void**)&pwh, g_wh);

    // 1) pre-pass: fp16 conversions
    prep_x<<<(M_ * F_ / 8) / 256, 256>>>(x, pxh);
    prep_w<<<dim3(32, 32, 3), dim3(32, 8)>>>(Wq, Wk, Wv, pwh);

    // 2) fp16 QKV projections (BK=32, 3-stage cp.async)
    cudaFuncSetAttribute(qkv_gemm_h,
                         cudaFuncAttributeMaxDynamicSharedMemorySize, GEMM_SMEM);
    qkv_gemm_h<<<dim3(F_ / 128, M_ / 128, 3), 256, GEMM_SMEM>>>(
        pxh, pwh, bq, bk, bv, pq, pk, pv);

    // 3) fp16 causal flash attention
    cudaFuncSetAttribute(flash_h,
                         cudaFuncAttributeMaxDynamicSharedMemorySize, FLASH_SMEM);
    flash_h<<<dim3(N_ / 128, B_ * H_), 256, FLASH_SMEM>>>(pq, pk, pv, out);
}

// round 15
// speedup vs baseline: 1.0738x; 1.0167x over previous
#include <cuda_runtime.h>
#include <cuda_fp16.h>
#include <math.h>
#include <stdint.h>

#define B_ 4
#define N_ 2048
#define F_ 1024
#define H_ 16
#define D_ 64
#define M_ (B_*N_)   // 8192 rows

// fp16 scratch. g_qh/g_kh: [b,h,n,d]; g_vh: TRANSPOSED [b,h,d,n].
__device__ __half g_qh[(size_t)B_*H_*N_*D_];
__device__ __half g_kh[(size_t)B_*H_*N_*D_];
__device__ __half g_vh[(size_t)B_*H_*N_*D_];
__device__ __half g_xh[(size_t)M_*F_];
__device__ __half g_wh[(size_t)3*F_*F_];

__device__ __forceinline__ float ex2f(float x) {
    float y;
    asm("ex2.approx.ftz.f32 %0, %1;" : "=f"(y) : "f"(x));
    return y;
}
__device__ __forceinline__ uint32_t smem_u32(const void* p) {
    uint32_t a;
    asm("{ .reg .u64 t; cvta.to.shared.u64 t, %1; cvt.u32.u64 %0, t; }" : "=r"(a) : "l"(p));
    return a;
}
__device__ __forceinline__ uint32_t f2h2(float lo, float hi) {
    uint32_t r;
    asm("cvt.rn.f16x2.f32 %0, %1, %2;" : "=r"(r) : "f"(hi), "f"(lo));
    return r;
}
__device__ __forceinline__ void mma16(float& d0, float& d1, float& d2, float& d3,
                                      uint32_t a0, uint32_t a1, uint32_t a2, uint32_t a3,
                                      uint32_t b0, uint32_t b1)
{
    asm volatile("mma.sync.aligned.m16n8k16.row.col.f32.f16.f16.f32 "
                 "{%0,%1,%2,%3}, {%4,%5,%6,%7}, {%8,%9}, {%0,%1,%2,%3};"
                 : "+f"(d0), "+f"(d1), "+f"(d2), "+f"(d3)
                 : "r"(a0), "r"(a1), "r"(a2), "r"(a3), "r"(b0), "r"(b1));
}
__device__ __forceinline__ void ldsm_x4(uint32_t& r0, uint32_t& r1, uint32_t& r2, uint32_t& r3,
                                        uint32_t addr)
{
    asm volatile("ldmatrix.sync.aligned.m8n8.x4.shared.b16 {%0,%1,%2,%3}, [%4];"
                 : "=r"(r0), "=r"(r1), "=r"(r2), "=r"(r3) : "r"(addr));
}
#define CP_ASYNC16(dst, src) \
    asm volatile("cp.async.cg.shared.global [%0], [%1], 16;" :: "r"(dst), "l"(src) : "memory")
#define CP_COMMIT() asm volatile("cp.async.commit_group;" ::: "memory")
#define CP_WAIT0()  asm volatile("cp.async.wait_group 0;" ::: "memory")

#define QSC_ 0.18033688011112042f   // 0.125 * log2(e)

// ---------------------------------------------------------------------------
// Pre-pass: X -> fp16; W -> fp16 W^T.
// ---------------------------------------------------------------------------
__global__ __launch_bounds__(256)
void prep_x(const float* __restrict__ X, __half* __restrict__ Xh)
{
    const size_t i = ((size_t)blockIdx.x * 256 + threadIdx.x) * 8;
    float4 v0 = *(const float4*)(X + i);
    float4 v1 = *(const float4*)(X + i + 4);
    uint4 r;
    r.x = f2h2(v0.x, v0.y);
    r.y = f2h2(v0.z, v0.w);
    r.z = f2h2(v1.x, v1.y);
    r.w = f2h2(v1.z, v1.w);
    *(uint4*)(Xh + i) = r;
}

__global__ __launch_bounds__(256)
void prep_w(const float* __restrict__ Wq, const float* __restrict__ Wk,
            const float* __restrict__ Wv, __half* __restrict__ Wh)
{
    __shared__ float t[32][33];
    const int z = blockIdx.z;
    const float* W = (z == 0) ? Wq : (z == 1) ? Wk : Wv;
    __half* o = Wh + (size_t)z * F_ * F_;
    const int x0 = blockIdx.x * 32, y0 = blockIdx.y * 32;
    const int tx = threadIdx.x, ty = threadIdx.y;
#pragma unroll
    for (int i = 0; i < 32; i += 8)
        t[ty + i][tx] = W[(size_t)(y0 + ty + i) * F_ + x0 + tx];
    __syncthreads();
#pragma unroll
    for (int i = 0; i < 32; i += 8)
        o[(size_t)(x0 + ty + i) * F_ + y0 + tx] = __float2half_rn(t[tx][ty + i]);
}

// ---------------------------------------------------------------------------
// fp16 GEMM: exact round-12 config (128x128, BK=32, 2-stage, LDSM; 180us).
// ---------------------------------------------------------------------------
#define GSTR 40
#define GSTG (128 * GSTR)
#define GEMM_SMEM (2 * 2 * GSTG * 2)              // 40960 B

__global__ __launch_bounds__(256, 2)
void qkv_gemm_h(const __half* __restrict__ Xh, const __half* __restrict__ Wh,
                const float* __restrict__ bi0, const float* __restrict__ bi1,
                const float* __restrict__ bi2,
                __half* __restrict__ o0, __half* __restrict__ o1,
                __half* __restrict__ o2)
{
    extern __shared__ __align__(16) __half gsm[];
    const int z = blockIdx.z;
    const __half* Wz  = Wh + (size_t)z * F_ * F_;
    const float* bias = (z == 0) ? bi0 : (z == 1) ? bi1 : bi2;
    __half* outp      = (z == 0) ? o0 : (z == 1) ? o1 : o2;
    const float sc    = (z == 0) ? QSC_ : 1.0f;

    const int tid  = threadIdx.x;
    const int lane = tid & 31;
    const int wid  = tid >> 5;
    const int wr   = wid & 1;
    const int wc   = wid >> 1;
    const int m0   = blockIdx.y * 128;
    const int n0   = blockIdx.x * 128;
    const int tg   = lane & 3;
    const int gp   = lane >> 2;

    const uint32_t sb = smem_u32(gsm);
    const uint32_t aoff[2] = {0, 2u * GSTG * 2};
    const uint32_t boff = GSTG * 2;

    const int lr = tid >> 1, lc = (tid & 1) * 16;
    const __half* srcA = Xh + (size_t)(m0 + lr) * F_ + lc;
    const __half* srcB = Wz + (size_t)(n0 + lr) * F_ + lc;

    {
        uint32_t da = sb + (lr * GSTR + lc) * 2;
        CP_ASYNC16(da, srcA); CP_ASYNC16(da + 16, srcA + 8);
        uint32_t db = sb + boff + (lr * GSTR + lc) * 2;
        CP_ASYNC16(db, srcB); CP_ASYNC16(db + 16, srcB + 8);
    }
    CP_COMMIT();
    CP_WAIT0();
    __syncthreads();

    float c[4][4][4];
#pragma unroll
    for (int i = 0; i < 4; i++)
#pragma unroll
        for (int j = 0; j < 4; j++)
#pragma unroll
            for (int r = 0; r < 4; r++) c[i][j][r] = 0.f;

    const int arow8 = ((lane >> 3) & 1) * 8 + (lane & 7);
    const int acol8 = ((lane >> 4) & 1) * 8;
    const int brow8 = ((lane >> 4) & 1) * 8 + (lane & 7);
    const int bcol8 = ((lane >> 3) & 1) * 8;

    int buf = 0;
    const int NT = F_ / 32;
    for (int kt = 0; kt < NT; kt++) {
        if (kt + 1 < NT) {
            const int kb = (kt + 1) * 32;
            uint32_t da = sb + aoff[buf ^ 1] + (lr * GSTR + lc) * 2;
            CP_ASYNC16(da, srcA + kb); CP_ASYNC16(da + 16, srcA + kb + 8);
            uint32_t db = sb + aoff[buf ^ 1] + boff + (lr * GSTR + lc) * 2;
            CP_ASYNC16(db, srcB + kb); CP_ASYNC16(db + 16, srcB + kb + 8);
            CP_COMMIT();
        }

        const uint32_t abase = sb + aoff[buf] + ((wr * 64 + arow8) * GSTR + acol8) * 2;
        const uint32_t bbase = sb + aoff[buf] + boff + ((wc * 32 + brow8) * GSTR + bcol8) * 2;

#pragma unroll
        for (int kk = 0; kk < 32; kk += 16) {
            uint32_t af[4][4], bf[2][4];
#pragma unroll
            for (int mt = 0; mt < 4; mt++)
                ldsm_x4(af[mt][0], af[mt][1], af[mt][2], af[mt][3],
                        abase + (mt * 16 * GSTR + kk) * 2);
#pragma unroll
            for (int h = 0; h < 2; h++)
                ldsm_x4(bf[h][0], bf[h][1], bf[h][2], bf[h][3],
                        bbase + (h * 16 * GSTR + kk) * 2);
#pragma unroll
            for (int mt = 0; mt < 4; mt++)
#pragma unroll
                for (int h = 0; h < 2; h++) {
                    mma16(c[mt][2*h][0], c[mt][2*h][1], c[mt][2*h][2], c[mt][2*h][3],
                          af[mt][0], af[mt][1], af[mt][2], af[mt][3],
                          bf[h][0], bf[h][1]);
                    mma16(c[mt][2*h+1][0], c[mt][2*h+1][1], c[mt][2*h+1][2], c[mt][2*h+1][3],
                          af[mt][0], af[mt][1], af[mt][2], af[mt][3],
                          bf[h][2], bf[h][3]);
                }
        }

        if (kt + 1 < NT) {
            CP_WAIT0();
            __syncthreads();
            buf ^= 1;
        }
    }

#pragma unroll
    for (int mt = 0; mt < 4; mt++) {
#pragma unroll
        for (int nt = 0; nt < 4; nt++) {
            const int j  = n0 + wc * 32 + nt * 8 + tg * 2;
            const int h  = j >> 6, dd = j & 63;
            const float bj0 = bias[j], bj1 = bias[j + 1];
            const int m  = m0 + wr * 64 + mt * 16 + gp;
            const int bb = m >> 11, nn = m & 2047;
            const float r00 = (c[mt][nt][0] + bj0) * sc;
            const float r01 = (c[mt][nt][1] + bj1) * sc;
            const float r10 = (c[mt][nt][2] + bj0) * sc;
            const float r11 = (c[mt][nt][3] + bj1) * sc;
            if (z == 2) {
                __half* bp = outp + (((size_t)(bb * H_ + h)) * D_ + dd) * N_ + nn;
                bp[0]      = __float2half_rn(r00);
                bp[N_]     = __float2half_rn(r01);
                bp[8]      = __float2half_rn(r10);
                bp[N_ + 8] = __float2half_rn(r11);
            } else {
                __half* bp = outp + (((size_t)(bb * H_ + h)) * N_ + nn) * D_ + dd;
                *(uint32_t*)bp = f2h2(r00, r01);
                *(uint32_t*)(bp + 8 * (size_t)D_) = f2h2(r10, r11);
            }
        }
    }
}

// ---------------------------------------------------------------------------
// fp16 flash v2: CTA = 256 Q rows, 8 warps x (32 rows x 64 cols).
// K/Vt b-frags loaded once per warp feed TWO m-tiles -> LDSM/MMA halved.
// Per-warp skip of fully-masked diagonal warp-tiles.
// ---------------------------------------------------------------------------
#define FSTR 72
#define FLASH_SMEM ((256*FSTR + 2*64*FSTR + 2*64*FSTR) * 2)   // 73728 B

__global__ __launch_bounds__(256, 1)
void flash_h(const __half* __restrict__ gq, const __half* __restrict__ gk,
             const __half* __restrict__ gvt, float* __restrict__ out)
{
    extern __shared__ __align__(16) __half fsm[];
    const uint32_t qs_base = smem_u32(fsm);
    const uint32_t ks_base = qs_base + 256 * FSTR * 2;
    const uint32_t vt_base = ks_base + 2 * 64 * FSTR * 2;

    const int tid = threadIdx.x, lane = tid & 31, wid = tid >> 5;
    const int gp = lane >> 2, tg = lane & 3;
    const int qt = (int)gridDim.x - 1 - (int)blockIdx.x;  // heavy tiles first
    const int bh = blockIdx.y;
    const int n0 = qt * 256;
    const int nkt = 4 * qt + 4;

    const __half* qb  = gq  + (size_t)bh * (N_ * D_);
    const __half* kb  = gk  + (size_t)bh * (N_ * D_);
    const __half* vtb = gvt + (size_t)bh * (D_ * N_);

    const int kr = tid >> 2, kc = (tid & 3) * 16;   // K/Vt: 4 thr/row, 16 fp16

    // prologue: Q (1 thr/row, 64 fp16) + K/Vt tile 0
    {
        const __half* src = qb + (size_t)(n0 + tid) * D_;
        uint32_t dst = qs_base + (tid * FSTR) * 2;
#pragma unroll
        for (int i = 0; i < 8; i++) CP_ASYNC16(dst + 16 * i, src + 8 * i);
    }
    {
        const __half* src = kb + (size_t)kr * D_ + kc;
        uint32_t dst = ks_base + (kr * FSTR + kc) * 2;
        CP_ASYNC16(dst, src); CP_ASYNC16(dst + 16, src + 8);
    }
    {
        const __half* src = vtb + (size_t)kr * N_ + kc;
        uint32_t dst = vt_base + (kr * FSTR + kc) * 2;
        CP_ASYNC16(dst, src); CP_ASYNC16(dst + 16, src + 8);
    }
    CP_COMMIT();
    CP_WAIT0();
    __syncthreads();

    // Q fragments: 2 m-tiles x 4 k-steps
    uint32_t qf[2][4][4];
    {
        const int qrow = wid * 32 + ((lane >> 3) & 1) * 8 + (lane & 7);
        const int qcol = ((lane >> 4) & 1) * 8;
#pragma unroll
        for (int mt = 0; mt < 2; mt++) {
            const uint32_t qaddr = qs_base + ((qrow + mt * 16) * FSTR + qcol) * 2;
#pragma unroll
            for (int ks = 0; ks < 4; ks++)
                ldsm_x4(qf[mt][ks][0], qf[mt][ks][1], qf[mt][ks][2], qf[mt][ks][3],
                        qaddr + (ks * 16) * 2);
        }
    }

    const int brow8 = ((lane >> 4) & 1) * 8 + (lane & 7);
    const int bcol8 = ((lane >> 3) & 1) * 8;

    // per-row-group state: idx = 2*mt + half  (rows gp+16mt, gp+8+16mt)
    float mr[4] = {-1e30f, -1e30f, -1e30f, -1e30f};
    float lr4[4] = {0.f, 0.f, 0.f, 0.f};
    float o[2][8][4];
#pragma unroll
    for (int mt = 0; mt < 2; mt++)
#pragma unroll
        for (int nt = 0; nt < 8; nt++)
#pragma unroll
            for (int e = 0; e < 4; e++) o[mt][nt][e] = 0.f;

    const int wrow_max = n0 + wid * 32 + 31;   // last row this warp owns

    int buf = 0;
    for (int kt = 0; kt < nkt; kt++) {
        const int c0 = kt * 64;
        const int more = (kt + 1 < nkt);

        if (more) {
            {
                const __half* src = kb + (size_t)(c0 + 64 + kr) * D_ + kc;
                uint32_t dst = ks_base + ((buf ^ 1) * 64 * FSTR + kr * FSTR + kc) * 2;
                CP_ASYNC16(dst, src); CP_ASYNC16(dst + 16, src + 8);
            }
            {
                const __half* src = vtb + (size_t)kr * N_ + c0 + 64 + kc;
                uint32_t dst = vt_base + ((buf ^ 1) * 64 * FSTR + kr * FSTR + kc) * 2;
                CP_ASYNC16(dst, src); CP_ASYNC16(dst + 16, src + 8);
            }
            CP_COMMIT();
        }

        if (c0 <= wrow_max) {   // skip fully-masked warp-tiles
            // --- S = Q K^T (32 x 64 per warp, shared b-frags) ---
            float s[2][8][4];
#pragma unroll
            for (int mt = 0; mt < 2; mt++)
#pragma unroll
                for (int nt = 0; nt < 8; nt++)
#pragma unroll
                    for (int e = 0; e < 4; e++) s[mt][nt][e] = 0.f;

            const uint32_t kaddr = ks_base + (buf * 64 * FSTR + brow8 * FSTR + bcol8) * 2;
#pragma unroll
            for (int n = 0; n < 4; n++) {
                const uint32_t an = kaddr + (n * 16 * FSTR) * 2;
#pragma unroll
                for (int ks = 0; ks < 4; ks++) {
                    uint32_t b0a, b1a, b0b, b1b;
                    ldsm_x4(b0a, b1a, b0b, b1b, an + (ks * 16) * 2);
#pragma unroll
                    for (int mt = 0; mt < 2; mt++) {
                        mma16(s[mt][2*n][0], s[mt][2*n][1], s[mt][2*n][2], s[mt][2*n][3],
                              qf[mt][ks][0], qf[mt][ks][1], qf[mt][ks][2], qf[mt][ks][3],
                              b0a, b1a);
                        mma16(s[mt][2*n+1][0], s[mt][2*n+1][1], s[mt][2*n+1][2], s[mt][2*n+1][3],
                              qf[mt][ks][0], qf[mt][ks][1], qf[mt][ks][2], qf[mt][ks][3],
                              b0b, b1b);
                    }
                }
            }

            // --- causal mask ---
            const int rbase = n0 + wid * 32 + gp;
            if (c0 + 63 > rbase) {   // diagonal region for this warp
#pragma unroll
                for (int mt = 0; mt < 2; mt++) {
                    const int i0g = rbase + mt * 16, i1g = i0g + 8;
#pragma unroll
                    for (int nt = 0; nt < 8; nt++) {
                        const int j0 = c0 + nt * 8 + 2 * tg;
                        if (j0     > i0g) s[mt][nt][0] = -1e30f;
                        if (j0 + 1 > i0g) s[mt][nt][1] = -1e30f;
                        if (j0     > i1g) s[mt][nt][2] = -1e30f;
                        if (j0 + 1 > i1g) s[mt][nt][3] = -1e30f;
                    }
                }
            }

            // --- online softmax (log2 domain), 4 row groups ---
#pragma unroll
            for (int mt = 0; mt < 2; mt++) {
                float mx0 = -1e30f, mx1 = -1e30f;
#pragma unroll
                for (int nt = 0; nt < 8; nt++) {
                    mx0 = fmaxf(mx0, fmaxf(s[mt][nt][0], s[mt][nt][1]));
                    mx1 = fmaxf(mx1, fmaxf(s[mt][nt][2], s[mt][nt][3]));
                }
                mx0 = fmaxf(mx0, __shfl_xor_sync(0xffffffffu, mx0, 1));
                mx0 = fmaxf(mx0, __shfl_xor_sync(0xffffffffu, mx0, 2));
                mx1 = fmaxf(mx1, __shfl_xor_sync(0xffffffffu, mx1, 1));
                mx1 = fmaxf(mx1, __shfl_xor_sync(0xffffffffu, mx1, 2));

                const float mn0 = fmaxf(mr[2*mt], mx0), mn1 = fmaxf(mr[2*mt+1], mx1);
                const float al0 = ex2f(mr[2*mt] - mn0), al1 = ex2f(mr[2*mt+1] - mn1);
                mr[2*mt] = mn0; mr[2*mt+1] = mn1;

                float ls0 = 0.f, ls1 = 0.f;
#pragma unroll
                for (int nt = 0; nt < 8; nt++) {
                    s[mt][nt][0] = ex2f(s[mt][nt][0] - mn0);
                    s[mt][nt][1] = ex2f(s[mt][nt][1] - mn0);
                    s[mt][nt][2] = ex2f(s[mt][nt][2] - mn1);
                    s[mt][nt][3] = ex2f(s[mt][nt][3] - mn1);
                    ls0 += s[mt][nt][0] + s[mt][nt][1];
                    ls1 += s[mt][nt][2] + s[mt][nt][3];
                }
                ls0 += __shfl_xor_sync(0xffffffffu, ls0, 1);
                ls0 += __shfl_xor_sync(0xffffffffu, ls0, 2);
                ls1 += __shfl_xor_sync(0xffffffffu, ls1, 1);
                ls1 += __shfl_xor_sync(0xffffffffu, ls1, 2);
                lr4[2*mt]   = lr4[2*mt]   * al0 + ls0;
                lr4[2*mt+1] = lr4[2*mt+1] * al1 + ls1;
#pragma unroll
                for (int nt = 0; nt < 8; nt++) {
                    o[mt][nt][0] *= al0; o[mt][nt][1] *= al0;
                    o[mt][nt][2] *= al1; o[mt][nt][3] *= al1;
                }
            }

            // --- O += P V (Vt b-frags shared across both m-tiles) ---
            const uint32_t vaddr = vt_base + (buf * 64 * FSTR + brow8 * FSTR + bcol8) * 2;
#pragma unroll
            for (int ks = 0; ks < 4; ks++) {
                uint32_t a[2][4];
#pragma unroll
                for (int mt = 0; mt < 2; mt++) {
                    a[mt][0] = f2h2(s[mt][2*ks][0],   s[mt][2*ks][1]);
                    a[mt][1] = f2h2(s[mt][2*ks][2],   s[mt][2*ks][3]);
                    a[mt][2] = f2h2(s[mt][2*ks+1][0], s[mt][2*ks+1][1]);
                    a[mt][3] = f2h2(s[mt][2*ks+1][2], s[mt][2*ks+1][3]);
                }
#pragma unroll
                for (int n = 0; n < 4; n++) {
                    uint32_t b0a, b1a, b0b, b1b;
                    ldsm_x4(b0a, b1a, b0b, b1b,
                            vaddr + (n * 16 * FSTR + ks * 16) * 2);
#pragma unroll
                    for (int mt = 0; mt < 2; mt++) {
                        mma16(o[mt][2*n][0], o[mt][2*n][1], o[mt][2*n][2], o[mt][2*n][3],
                              a[mt][0], a[mt][1], a[mt][2], a[mt][3], b0a, b1a);
                        mma16(o[mt][2*n+1][0], o[mt][2*n+1][1], o[mt][2*n+1][2], o[mt][2*n+1][3],
                              a[mt][0], a[mt][1], a[mt][2], a[mt][3], b0b, b1b);
                    }
                }
            }
        }

        if (more) {
            CP_WAIT0();
            __syncthreads();
            buf ^= 1;
        }
    }

    // --- normalize and write out [B, N, F] ---
    const int bb = bh >> 4, h = bh & 15;
#pragma unroll
    for (int mt = 0; mt < 2; mt++) {
        const int row = n0 + wid * 32 + mt * 16 + gp;
        const float inv0 = 1.f / lr4[2*mt], inv1 = 1.f / lr4[2*mt+1];
        float* base = out + ((size_t)(bb * N_ + row)) * F_ + h * D_;
#pragma unroll
        for (int nt = 0; nt < 8; nt++) {
            const int d = nt * 8 + 2 * tg;
            *(float2*)(base + d) =
                make_float2(o[mt][nt][0] * inv0, o[mt][nt][1] * inv0);
            *(float2*)(base + 8 * F_ + d) =
                make_float2(o[mt][nt][2] * inv1, o[mt][nt][3] * inv1);
        }
    }
}

// ---------------------------------------------------------------------------
extern "C" void kernel_launch(void* const* d_in, const int* in_sizes, int n_in,
                              void* d_out, int out_size)
{
    const float* x  = (const float*)d_in[0];
    const float* Wq = (const float*)d_in[1];
    const float* bq = (const float*)d_in[2];
    const float* Wk = (const float*)d_in[3];
    const float* bk = (const float*)d_in[4];
    const float* Wv = (const float*)d_in[5];
    const float* bv = (const float*)d_in[6];
    float* out = (float*)d_out;
    (void)in_sizes; (void)n_in; (void)out_size;

    __half *pq = nullptr, *pk = nullptr, *pv = nullptr, *pxh = nullptr, *pwh = nullptr;
    cudaGetSymbolAddress((void**)&pq, g_qh);
    cudaGetSymbolAddress((void**)&pk, g_kh);
    cudaGetSymbolAddress((void**)&pv, g_vh);
    cudaGetSymbolAddress((void**)&pxh, g_xh);
    cudaGetSymbolAddress((void**)&pwh, g_wh);

    prep_x<<<(M_ * F_ / 8) / 256, 256>>>(x, pxh);
    prep_w<<<dim3(32, 32, 3), dim3(32, 8)>>>(Wq, Wk, Wv, pwh);

    cudaFuncSetAttribute(qkv_gemm_h,
                         cudaFuncAttributeMaxDynamicSharedMemorySize, GEMM_SMEM);
    qkv_gemm_h<<<dim3(F_ / 128, M_ / 128, 3), 256, GEMM_SMEM>>>(
        pxh, pwh, bq, bk, bv, pq, pk, pv);

    cudaFuncSetAttribute(flash_h,
                         cudaFuncAttributeMaxDynamicSharedMemorySize, FLASH_SMEM);
    flash_h<<<dim3(N_ / 256, B_ * H_), 256, FLASH_SMEM>>>(pq, pk, pv, out);
}

// round 16
// speedup vs baseline: 1.0815x; 1.0072x over previous
#include <cuda_runtime.h>
#include <cuda_fp16.h>
#include <math.h>
#include <stdint.h>

#define B_ 4
#define N_ 2048
#define F_ 1024
#define H_ 16
#define D_ 64
#define M_ (B_*N_)   // 8192 rows

// fp16 scratch. g_qh/g_kh: [b,h,n,d]; g_vh: TRANSPOSED [b,h,d,n].
__device__ __half g_qh[(size_t)B_*H_*N_*D_];
__device__ __half g_kh[(size_t)B_*H_*N_*D_];
__device__ __half g_vh[(size_t)B_*H_*N_*D_];
__device__ __half g_xh[(size_t)M_*F_];
__device__ __half g_wh[(size_t)3*F_*F_];

__device__ __forceinline__ float ex2f(float x) {
    float y;
    asm("ex2.approx.ftz.f32 %0, %1;" : "=f"(y) : "f"(x));
    return y;
}
__device__ __forceinline__ uint32_t smem_u32(const void* p) {
    uint32_t a;
    asm("{ .reg .u64 t; cvta.to.shared.u64 t, %1; cvt.u32.u64 %0, t; }" : "=r"(a) : "l"(p));
    return a;
}
__device__ __forceinline__ uint32_t f2h2(float lo, float hi) {
    uint32_t r;
    asm("cvt.rn.f16x2.f32 %0, %1, %2;" : "=r"(r) : "f"(hi), "f"(lo));
    return r;
}
__device__ __forceinline__ void mma16(float& d0, float& d1, float& d2, float& d3,
                                      uint32_t a0, uint32_t a1, uint32_t a2, uint32_t a3,
                                      uint32_t b0, uint32_t b1)
{
    asm volatile("mma.sync.aligned.m16n8k16.row.col.f32.f16.f16.f32 "
                 "{%0,%1,%2,%3}, {%4,%5,%6,%7}, {%8,%9}, {%0,%1,%2,%3};"
                 : "+f"(d0), "+f"(d1), "+f"(d2), "+f"(d3)
                 : "r"(a0), "r"(a1), "r"(a2), "r"(a3), "r"(b0), "r"(b1));
}
__device__ __forceinline__ void ldsm_x4(uint32_t& r0, uint32_t& r1, uint32_t& r2, uint32_t& r3,
                                        uint32_t addr)
{
    asm volatile("ldmatrix.sync.aligned.m8n8.x4.shared.b16 {%0,%1,%2,%3}, [%4];"
                 : "=r"(r0), "=r"(r1), "=r"(r2), "=r"(r3) : "r"(addr));
}
#define CP_ASYNC16(dst, src) \
    asm volatile("cp.async.cg.shared.global [%0], [%1], 16;" :: "r"(dst), "l"(src) : "memory")
#define CP_COMMIT() asm volatile("cp.async.commit_group;" ::: "memory")
#define CP_WAIT0()  asm volatile("cp.async.wait_group 0;" ::: "memory")

#define QSC_ 0.18033688011112042f   // 0.125 * log2(e)

// ---------------------------------------------------------------------------
// Fused pre-pass (ONE launch): blocks [0,4096) convert X -> fp16;
// blocks [4096,7168) transpose+convert W -> fp16 W^T.
// ---------------------------------------------------------------------------
#define PREP_XBLOCKS (M_ * F_ / 8 / 256)   // 4096
#define PREP_WBLOCKS (3 * 32 * 32)         // 3072

__global__ __launch_bounds__(256)
void prep_all(const float* __restrict__ X,
              const float* __restrict__ Wq, const float* __restrict__ Wk,
              const float* __restrict__ Wv,
              __half* __restrict__ Xh, __half* __restrict__ Wh)
{
    __shared__ float t[32][33];
    const int tid = threadIdx.x;

    if (blockIdx.x < PREP_XBLOCKS) {
        const size_t i = ((size_t)blockIdx.x * 256 + tid) * 8;
        float4 v0 = *(const float4*)(X + i);
        float4 v1 = *(const float4*)(X + i + 4);
        uint4 r;
        r.x = f2h2(v0.x, v0.y);
        r.y = f2h2(v0.z, v0.w);
        r.z = f2h2(v1.x, v1.y);
        r.w = f2h2(v1.z, v1.w);
        *(uint4*)(Xh + i) = r;
    } else {
        const int w = blockIdx.x - PREP_XBLOCKS;
        const int z = w >> 10;                 // / 1024
        const int rem = w & 1023;
        const int x0 = (rem & 31) * 32;        // n block
        const int y0 = (rem >> 5) * 32;        // k block
        const float* W = (z == 0) ? Wq : (z == 1) ? Wk : Wv;
        __half* o = Wh + (size_t)z * F_ * F_;
        const int tx = tid & 31, ty = tid >> 5;   // 32 x 8
#pragma unroll
        for (int i = 0; i < 32; i += 8)
            t[ty + i][tx] = W[(size_t)(y0 + ty + i) * F_ + x0 + tx];
        __syncthreads();
#pragma unroll
        for (int i = 0; i < 32; i += 8)
            o[(size_t)(x0 + ty + i) * F_ + y0 + tx] = __float2half_rn(t[tx][ty + i]);
    }
}

// ---------------------------------------------------------------------------
// fp16 GEMM: exact round-12 config (128x128, BK=32, 2-stage, LDSM; ~180us).
// ---------------------------------------------------------------------------
#define GSTR 40
#define GSTG (128 * GSTR)
#define GEMM_SMEM (2 * 2 * GSTG * 2)              // 40960 B

__global__ __launch_bounds__(256, 2)
void qkv_gemm_h(const __half* __restrict__ Xh, const __half* __restrict__ Wh,
                const float* __restrict__ bi0, const float* __restrict__ bi1,
                const float* __restrict__ bi2,
                __half* __restrict__ o0, __half* __restrict__ o1,
                __half* __restrict__ o2)
{
    extern __shared__ __align__(16) __half gsm[];
    const int z = blockIdx.z;
    const __half* Wz  = Wh + (size_t)z * F_ * F_;
    const float* bias = (z == 0) ? bi0 : (z == 1) ? bi1 : bi2;
    __half* outp      = (z == 0) ? o0 : (z == 1) ? o1 : o2;
    const float sc    = (z == 0) ? QSC_ : 1.0f;

    const int tid  = threadIdx.x;
    const int lane = tid & 31;
    const int wid  = tid >> 5;
    const int wr   = wid & 1;
    const int wc   = wid >> 1;
    const int m0   = blockIdx.y * 128;
    const int n0   = blockIdx.x * 128;
    const int tg   = lane & 3;
    const int gp   = lane >> 2;

    const uint32_t sb = smem_u32(gsm);
    const uint32_t aoff[2] = {0, 2u * GSTG * 2};
    const uint32_t boff = GSTG * 2;

    const int lr = tid >> 1, lc = (tid & 1) * 16;
    const __half* srcA = Xh + (size_t)(m0 + lr) * F_ + lc;
    const __half* srcB = Wz + (size_t)(n0 + lr) * F_ + lc;

    {
        uint32_t da = sb + (lr * GSTR + lc) * 2;
        CP_ASYNC16(da, srcA); CP_ASYNC16(da + 16, srcA + 8);
        uint32_t db = sb + boff + (lr * GSTR + lc) * 2;
        CP_ASYNC16(db, srcB); CP_ASYNC16(db + 16, srcB + 8);
    }
    CP_COMMIT();
    CP_WAIT0();
    __syncthreads();

    float c[4][4][4];
#pragma unroll
    for (int i = 0; i < 4; i++)
#pragma unroll
        for (int j = 0; j < 4; j++)
#pragma unroll
            for (int r = 0; r < 4; r++) c[i][j][r] = 0.f;

    const int arow8 = ((lane >> 3) & 1) * 8 + (lane & 7);
    const int acol8 = ((lane >> 4) & 1) * 8;
    const int brow8 = ((lane >> 4) & 1) * 8 + (lane & 7);
    const int bcol8 = ((lane >> 3) & 1) * 8;

    int buf = 0;
    const int NT = F_ / 32;
    for (int kt = 0; kt < NT; kt++) {
        if (kt + 1 < NT) {
            const int kb = (kt + 1) * 32;
            uint32_t da = sb + aoff[buf ^ 1] + (lr * GSTR + lc) * 2;
            CP_ASYNC16(da, srcA + kb); CP_ASYNC16(da + 16, srcA + kb + 8);
            uint32_t db = sb + aoff[buf ^ 1] + boff + (lr * GSTR + lc) * 2;
            CP_ASYNC16(db, srcB + kb); CP_ASYNC16(db + 16, srcB + kb + 8);
            CP_COMMIT();
        }

        const uint32_t abase = sb + aoff[buf] + ((wr * 64 + arow8) * GSTR + acol8) * 2;
        const uint32_t bbase = sb + aoff[buf] + boff + ((wc * 32 + brow8) * GSTR + bcol8) * 2;

#pragma unroll
        for (int kk = 0; kk < 32; kk += 16) {
            uint32_t af[4][4], bf[2][4];
#pragma unroll
            for (int mt = 0; mt < 4; mt++)
                ldsm_x4(af[mt][0], af[mt][1], af[mt][2], af[mt][3],
                        abase + (mt * 16 * GSTR + kk) * 2);
#pragma unroll
            for (int h = 0; h < 2; h++)
                ldsm_x4(bf[h][0], bf[h][1], bf[h][2], bf[h][3],
                        bbase + (h * 16 * GSTR + kk) * 2);
#pragma unroll
            for (int mt = 0; mt < 4; mt++)
#pragma unroll
                for (int h = 0; h < 2; h++) {
                    mma16(c[mt][2*h][0], c[mt][2*h][1], c[mt][2*h][2], c[mt][2*h][3],
                          af[mt][0], af[mt][1], af[mt][2], af[mt][3],
                          bf[h][0], bf[h][1]);
                    mma16(c[mt][2*h+1][0], c[mt][2*h+1][1], c[mt][2*h+1][2], c[mt][2*h+1][3],
                          af[mt][0], af[mt][1], af[mt][2], af[mt][3],
                          bf[h][2], bf[h][3]);
                }
        }

        if (kt + 1 < NT) {
            CP_WAIT0();
            __syncthreads();
            buf ^= 1;
        }
    }

#pragma unroll
    for (int mt = 0; mt < 4; mt++) {
#pragma unroll
        for (int nt = 0; nt < 4; nt++) {
            const int j  = n0 + wc * 32 + nt * 8 + tg * 2;
            const int h  = j >> 6, dd = j & 63;
            const float bj0 = bias[j], bj1 = bias[j + 1];
            const int m  = m0 + wr * 64 + mt * 16 + gp;
            const int bb = m >> 11, nn = m & 2047;
            const float r00 = (c[mt][nt][0] + bj0) * sc;
            const float r01 = (c[mt][nt][1] + bj1) * sc;
            const float r10 = (c[mt][nt][2] + bj0) * sc;
            const float r11 = (c[mt][nt][3] + bj1) * sc;
            if (z == 2) {
                __half* bp = outp + (((size_t)(bb * H_ + h)) * D_ + dd) * N_ + nn;
                bp[0]      = __float2half_rn(r00);
                bp[N_]     = __float2half_rn(r01);
                bp[8]      = __float2half_rn(r10);
                bp[N_ + 8] = __float2half_rn(r11);
            } else {
                __half* bp = outp + (((size_t)(bb * H_ + h)) * N_ + nn) * D_ + dd;
                *(uint32_t*)bp = f2h2(r00, r01);
                *(uint32_t*)(bp + 8 * (size_t)D_) = f2h2(r10, r11);
            }
        }
    }
}

// ---------------------------------------------------------------------------
// fp16 flash v2 (exact round-15, passing, 144.8us): CTA = 256 Q rows,
// 8 warps x (32 x 64), shared b-frags, per-warp diagonal skip.
// ---------------------------------------------------------------------------
#define FSTR 72
#define FLASH_SMEM ((256*FSTR + 2*64*FSTR + 2*64*FSTR) * 2)   // 73728 B

__global__ __launch_bounds__(256, 1)
void flash_h(const __half* __restrict__ gq, const __half* __restrict__ gk,
             const __half* __restrict__ gvt, float* __restrict__ out)
{
    extern __shared__ __align__(16) __half fsm[];
    const uint32_t qs_base = smem_u32(fsm);
    const uint32_t ks_base = qs_base + 256 * FSTR * 2;
    const uint32_t vt_base = ks_base + 2 * 64 * FSTR * 2;

    const int tid = threadIdx.x, lane = tid & 31, wid = tid >> 5;
    const int gp = lane >> 2, tg = lane & 3;
    const int qt = (int)gridDim.x - 1 - (int)blockIdx.x;
    const int bh = blockIdx.y;
    const int n0 = qt * 256;
    const int nkt = 4 * qt + 4;

    const __half* qb  = gq  + (size_t)bh * (N_ * D_);
    const __half* kb  = gk  + (size_t)bh * (N_ * D_);
    const __half* vtb = gvt + (size_t)bh * (D_ * N_);

    const int kr = tid >> 2, kc = (tid & 3) * 16;

    {
        const __half* src = qb + (size_t)(n0 + tid) * D_;
        uint32_t dst = qs_base + (tid * FSTR) * 2;
#pragma unroll
        for (int i = 0; i < 8; i++) CP_ASYNC16(dst + 16 * i, src + 8 * i);
    }
    {
        const __half* src = kb + (size_t)kr * D_ + kc;
        uint32_t dst = ks_base + (kr * FSTR + kc) * 2;
        CP_ASYNC16(dst, src); CP_ASYNC16(dst + 16, src + 8);
    }
    {
        const __half* src = vtb + (size_t)kr * N_ + kc;
        uint32_t dst = vt_base + (kr * FSTR + kc) * 2;
        CP_ASYNC16(dst, src); CP_ASYNC16(dst + 16, src + 8);
    }
    CP_COMMIT();
    CP_WAIT0();
    __syncthreads();

    uint32_t qf[2][4][4];
    {
        const int qrow = wid * 32 + ((lane >> 3) & 1) * 8 + (lane & 7);
        const int qcol = ((lane >> 4) & 1) * 8;
#pragma unroll
        for (int mt = 0; mt < 2; mt++) {
            const uint32_t qaddr = qs_base + ((qrow + mt * 16) * FSTR + qcol) * 2;
#pragma unroll
            for (int ks = 0; ks < 4; ks++)
                ldsm_x4(qf[mt][ks][0], qf[mt][ks][1], qf[mt][ks][2], qf[mt][ks][3],
                        qaddr + (ks * 16) * 2);
        }
    }

    const int brow8 = ((lane >> 4) & 1) * 8 + (lane & 7);
    const int bcol8 = ((lane >> 3) & 1) * 8;

    float mr[4] = {-1e30f, -1e30f, -1e30f, -1e30f};
    float lr4[4] = {0.f, 0.f, 0.f, 0.f};
    float o[2][8][4];
#pragma unroll
    for (int mt = 0; mt < 2; mt++)
#pragma unroll
        for (int nt = 0; nt < 8; nt++)
#pragma unroll
            for (int e = 0; e < 4; e++) o[mt][nt][e] = 0.f;

    const int wrow_max = n0 + wid * 32 + 31;

    int buf = 0;
    for (int kt = 0; kt < nkt; kt++) {
        const int c0 = kt * 64;
        const int more = (kt + 1 < nkt);

        if (more) {
            {
                const __half* src = kb + (size_t)(c0 + 64 + kr) * D_ + kc;
                uint32_t dst = ks_base + ((buf ^ 1) * 64 * FSTR + kr * FSTR + kc) * 2;
                CP_ASYNC16(dst, src); CP_ASYNC16(dst + 16, src + 8);
            }
            {
                const __half* src = vtb + (size_t)kr * N_ + c0 + 64 + kc;
                uint32_t dst = vt_base + ((buf ^ 1) * 64 * FSTR + kr * FSTR + kc) * 2;
                CP_ASYNC16(dst, src); CP_ASYNC16(dst + 16, src + 8);
            }
            CP_COMMIT();
        }

        if (c0 <= wrow_max) {
            float s[2][8][4];
#pragma unroll
            for (int mt = 0; mt < 2; mt++)
#pragma unroll
                for (int nt = 0; nt < 8; nt++)
#pragma unroll
                    for (int e = 0; e < 4; e++) s[mt][nt][e] = 0.f;

            const uint32_t kaddr = ks_base + (buf * 64 * FSTR + brow8 * FSTR + bcol8) * 2;
#pragma unroll
            for (int n = 0; n < 4; n++) {
                const uint32_t an = kaddr + (n * 16 * FSTR) * 2;
#pragma unroll
                for (int ks = 0; ks < 4; ks++) {
                    uint32_t b0a, b1a, b0b, b1b;
                    ldsm_x4(b0a, b1a, b0b, b1b, an + (ks * 16) * 2);
#pragma unroll
                    for (int mt = 0; mt < 2; mt++) {
                        mma16(s[mt][2*n][0], s[mt][2*n][1], s[mt][2*n][2], s[mt][2*n][3],
                              qf[mt][ks][0], qf[mt][ks][1], qf[mt][ks][2], qf[mt][ks][3],
                              b0a, b1a);
                        mma16(s[mt][2*n+1][0], s[mt][2*n+1][1], s[mt][2*n+1][2], s[mt][2*n+1][3],
                              qf[mt][ks][0], qf[mt][ks][1], qf[mt][ks][2], qf[mt][ks][3],
                              b0b, b1b);
                    }
                }
            }

            const int rbase = n0 + wid * 32 + gp;
            if (c0 + 63 > rbase) {
#pragma unroll
                for (int mt = 0; mt < 2; mt++) {
                    const int i0g = rbase + mt * 16, i1g = i0g + 8;
#pragma unroll
                    for (int nt = 0; nt < 8; nt++) {
                        const int j0 = c0 + nt * 8 + 2 * tg;
                        if (j0     > i0g) s[mt][nt][0] = -1e30f;
                        if (j0 + 1 > i0g) s[mt][nt][1] = -1e30f;
                        if (j0     > i1g) s[mt][nt][2] = -1e30f;
                        if (j0 + 1 > i1g) s[mt][nt][3] = -1e30f;
                    }
                }
            }

#pragma unroll
            for (int mt = 0; mt < 2; mt++) {
                float mx0 = -1e30f, mx1 = -1e30f;
#pragma unroll
                for (int nt = 0; nt < 8; nt++) {
                    mx0 = fmaxf(mx0, fmaxf(s[mt][nt][0], s[mt][nt][1]));
                    mx1 = fmaxf(mx1, fmaxf(s[mt][nt][2], s[mt][nt][3]));
                }
                mx0 = fmaxf(mx0, __shfl_xor_sync(0xffffffffu, mx0, 1));
                mx0 = fmaxf(mx0, __shfl_xor_sync(0xffffffffu, mx0, 2));
                mx1 = fmaxf(mx1, __shfl_xor_sync(0xffffffffu, mx1, 1));
                mx1 = fmaxf(mx1, __shfl_xor_sync(0xffffffffu, mx1, 2));

                const float mn0 = fmaxf(mr[2*mt], mx0), mn1 = fmaxf(mr[2*mt+1], mx1);
                const float al0 = ex2f(mr[2*mt] - mn0), al1 = ex2f(mr[2*mt+1] - mn1);
                mr[2*mt] = mn0; mr[2*mt+1] = mn1;

                float ls0 = 0.f, ls1 = 0.f;
#pragma unroll
                for (int nt = 0; nt < 8; nt++) {
                    s[mt][nt][0] = ex2f(s[mt][nt][0] - mn0);
                    s[mt][nt][1] = ex2f(s[mt][nt][1] - mn0);
                    s[mt][nt][2] = ex2f(s[mt][nt][2] - mn1);
                    s[mt][nt][3] = ex2f(s[mt][nt][3] - mn1);
                    ls0 += s[mt][nt][0] + s[mt][nt][1];
                    ls1 += s[mt][nt][2] + s[mt][nt][3];
                }
                ls0 += __shfl_xor_sync(0xffffffffu, ls0, 1);
                ls0 += __shfl_xor_sync(0xffffffffu, ls0, 2);
                ls1 += __shfl_xor_sync(0xffffffffu, ls1, 1);
                ls1 += __shfl_xor_sync(0xffffffffu, ls1, 2);
                lr4[2*mt]   = lr4[2*mt]   * al0 + ls0;
                lr4[2*mt+1] = lr4[2*mt+1] * al1 + ls1;
#pragma unroll
                for (int nt = 0; nt < 8; nt++) {
                    o[mt][nt][0] *= al0; o[mt][nt][1] *= al0;
                    o[mt][nt][2] *= al1; o[mt][nt][3] *= al1;
                }
            }

            const uint32_t vaddr = vt_base + (buf * 64 * FSTR + brow8 * FSTR + bcol8) * 2;
#pragma unroll
            for (int ks = 0; ks < 4; ks++) {
                uint32_t a[2][4];
#pragma unroll
                for (int mt = 0; mt < 2; mt++) {
                    a[mt][0] = f2h2(s[mt][2*ks][0],   s[mt][2*ks][1]);
                    a[mt][1] = f2h2(s[mt][2*ks][2],   s[mt][2*ks][3]);
                    a[mt][2] = f2h2(s[mt][2*ks+1][0], s[mt][2*ks+1][1]);
                    a[mt][3] = f2h2(s[mt][2*ks+1][2], s[mt][2*ks+1][3]);
                }
#pragma unroll
                for (int n = 0; n < 4; n++) {
                    uint32_t b0a, b1a, b0b, b1b;
                    ldsm_x4(b0a, b1a, b0b, b1b,
                            vaddr + (n * 16 * FSTR + ks * 16) * 2);
#pragma unroll
                    for (int mt = 0; mt < 2; mt++) {
                        mma16(o[mt][2*n][0], o[mt][2*n][1], o[mt][2*n][2], o[mt][2*n][3],
                              a[mt][0], a[mt][1], a[mt][2], a[mt][3], b0a, b1a);
                        mma16(o[mt][2*n+1][0], o[mt][2*n+1][1], o[mt][2*n+1][2], o[mt][2*n+1][3],
                              a[mt][0], a[mt][1], a[mt][2], a[mt][3], b0b, b1b);
                    }
                }
            }
        }

        if (more) {
            CP_WAIT0();
            __syncthreads();
            buf ^= 1;
        }
    }

    const int bb = bh >> 4, h = bh & 15;
#pragma unroll
    for (int mt = 0; mt < 2; mt++) {
        const int row = n0 + wid * 32 + mt * 16 + gp;
        const float inv0 = 1.f / lr4[2*mt], inv1 = 1.f / lr4[2*mt+1];
        float* base = out + ((size_t)(bb * N_ + row)) * F_ + h * D_;
#pragma unroll
        for (int nt = 0; nt < 8; nt++) {
            const int d = nt * 8 + 2 * tg;
            *(float2*)(base + d) =
                make_float2(o[mt][nt][0] * inv0, o[mt][nt][1] * inv0);
            *(float2*)(base + 8 * F_ + d) =
                make_float2(o[mt][nt][2] * inv1, o[mt][nt][3] * inv1);
        }
    }
}

// ---------------------------------------------------------------------------
extern "C" void kernel_launch(void* const* d_in, const int* in_sizes, int n_in,
                              void* d_out, int out_size)
{
    const float* x  = (const float*)d_in[0];
    const float* Wq = (const float*)d_in[1];
    const float* bq = (const float*)d_in[2];
    const float* Wk = (const float*)d_in[3];
    const float* bk = (const float*)d_in[4];
    const float* Wv = (const float*)d_in[5];
    const float* bv = (const float*)d_in[6];
    float* out = (float*)d_out;
    (void)in_sizes; (void)n_in; (void)out_size;

    __half *pq = nullptr, *pk = nullptr, *pv = nullptr, *pxh = nullptr, *pwh = nullptr;
    cudaGetSymbolAddress((void**)&pq, g_qh);
    cudaGetSymbolAddress((void**)&pk, g_kh);
    cudaGetSymbolAddress((void**)&pv, g_vh);
    cudaGetSymbolAddress((void**)&pxh, g_xh);
    cudaGetSymbolAddress((void**)&pwh, g_wh);

    // 1) fused pre-pass (one launch)
    prep_all<<<PREP_XBLOCKS + PREP_WBLOCKS, 256>>>(x, Wq, Wk, Wv, pxh, pwh);

    // 2) fp16 QKV projections (round-12 config)
    cudaFuncSetAttribute(qkv_gemm_h,
                         cudaFuncAttributeMaxDynamicSharedMemorySize, GEMM_SMEM);
    qkv_gemm_h<<<dim3(F_ / 128, M_ / 128, 3), 256, GEMM_SMEM>>>(
        pxh, pwh, bq, bk, bv, pq, pk, pv);

    // 3) fp16 causal flash attention (round-15 config)
    cudaFuncSetAttribute(flash_h,
                         cudaFuncAttributeMaxDynamicSharedMemorySize, FLASH_SMEM);
    flash_h<<<dim3(N_ / 256, B_ * H_), 256, FLASH_SMEM>>>(pq, pk, pv, out);
}